// round 7
// baseline (speedup 1.0000x reference)
#include <cuda_runtime.h>
#include <stdint.h>

// Scratch: per-node scalar weight accumulator. Max N_NODES = 100000.
#define MAX_NODES 100000
__device__ float g_S[MAX_NODES];

__global__ void zero_kernel(int n_vec4) {
    int i = blockIdx.x * blockDim.x + threadIdx.x;
    if (i < n_vec4)
        reinterpret_cast<float4*>(g_S)[i] = make_float4(0.f, 0.f, 0.f, 0.f);
}

// Per-edge: S[target[e]] += W[e]. Eight edges per thread.
// edge_index is INT32 (JAX default config downgrades int64 -> int32).
// 2x int4 (indices) + 2x float4 (weights) front-batched -> MLP=4 to hide DRAM latency.
__global__ void edge_kernel(const int* __restrict__ target,
                            const float* __restrict__ W, int E) {
    int i = blockIdx.x * blockDim.x + threadIdx.x;
    int e = i * 8;
    if (e + 7 < E) {
        int4   ta = *reinterpret_cast<const int4*>(target + e);
        int4   tb = *reinterpret_cast<const int4*>(target + e + 4);
        float4 wa = *reinterpret_cast<const float4*>(W + e);
        float4 wb = *reinterpret_cast<const float4*>(W + e + 4);
        int idx[8] = {ta.x, ta.y, ta.z, ta.w, tb.x, tb.y, tb.z, tb.w};
        float w[8] = {wa.x, wa.y, wa.z, wa.w, wb.x, wb.y, wb.z, wb.w};
        #pragma unroll
        for (int k = 0; k < 8; k++) {
            // guard: never fault even if layout assumption is wrong (costs 1 ISETP)
            if ((unsigned)idx[k] < (unsigned)MAX_NODES)
                atomicAdd(&g_S[idx[k]], w[k]);
        }
    } else {
        for (; e < E; e++) {
            int t = target[e];
            if ((unsigned)t < (unsigned)MAX_NODES)
                atomicAdd(&g_S[t], W[e]);
        }
    }
}

// Per-node scale: out[n, :] = x[n, :] * S[n].
// D_FEAT = 32 floats = 8 float4 per node; 8 consecutive threads share one S value.
__global__ void scale_kernel(const float4* __restrict__ x4,
                             float4* __restrict__ out4, int n_vec4) {
    int i = blockIdx.x * blockDim.x + threadIdx.x;
    if (i < n_vec4) {
        float s = g_S[i >> 3];
        float4 v = x4[i];
        v.x *= s; v.y *= s; v.z *= s; v.w *= s;
        out4[i] = v;
    }
}

extern "C" void kernel_launch(void* const* d_in, const int* in_sizes, int n_in,
                              void* d_out, int out_size) {
    const int*   edge_index = (const int*)d_in[0];    // [2, E] int32, row-major
    const float* x          = (const float*)d_in[1];  // [N, 32] float32
    const float* W          = (const float*)d_in[2];  // [E] float32

    int E = in_sizes[2];
    int n_nodes = out_size / 32;             // output is [N, 32] float32
    const int* target = edge_index + E;      // row 1 (targets)

    // 1) zero the per-node accumulator (100000 / 4 = 25000 float4)
    {
        int n_vec4 = (n_nodes + 3) / 4;
        int threads = 256;
        int blocks = (n_vec4 + threads - 1) / threads;
        zero_kernel<<<blocks, threads>>>(n_vec4);
    }
    // 2) scatter-add edge weights onto target nodes
    {
        int threads = 256;
        int work = (E + 7) / 8;
        int blocks = (work + threads - 1) / threads;
        edge_kernel<<<blocks, threads>>>(target, W, E);
    }
    // 3) scale node features by accumulated weight
    {
        int n_vec4 = n_nodes * 8;  // 32 floats / 4
        int threads = 256;
        int blocks = (n_vec4 + threads - 1) / threads;
        scale_kernel<<<blocks, threads>>>((const float4*)x, (float4*)d_out, n_vec4);
    }
}

// round 10
// speedup vs baseline: 1.1254x; 1.1254x over previous
#include <cuda_runtime.h>
#include <stdint.h>

// Per-node scalar weight accumulator. __device__ globals are zero-initialized
// at module load; scale_kernel resets each entry to 0 after consuming it, so
// every kernel_launch (and every graph replay) starts from a zeroed array.
// Deterministic: identical work on every call.
#define MAX_NODES 100000
__device__ float g_S[MAX_NODES];

// Per-edge: S[target[e]] += W[e]. Eight edges per thread.
// edge_index is INT32. 2x int4 + 2x float4 front-batched -> MLP=4.
__global__ void edge_kernel(const int* __restrict__ target,
                            const float* __restrict__ W, int E) {
    int i = blockIdx.x * blockDim.x + threadIdx.x;
    int e = i * 8;
    if (e + 7 < E) {
        int4   ta = *reinterpret_cast<const int4*>(target + e);
        int4   tb = *reinterpret_cast<const int4*>(target + e + 4);
        float4 wa = *reinterpret_cast<const float4*>(W + e);
        float4 wb = *reinterpret_cast<const float4*>(W + e + 4);
        int idx[8] = {ta.x, ta.y, ta.z, ta.w, tb.x, tb.y, tb.z, tb.w};
        float w[8] = {wa.x, wa.y, wa.z, wa.w, wb.x, wb.y, wb.z, wb.w};
        #pragma unroll
        for (int k = 0; k < 8; k++) {
            if ((unsigned)idx[k] < (unsigned)MAX_NODES)
                atomicAdd(&g_S[idx[k]], w[k]);
        }
    } else {
        for (; e < E; e++) {
            int t = target[e];
            if ((unsigned)t < (unsigned)MAX_NODES)
                atomicAdd(&g_S[t], W[e]);
        }
    }
}

// Per-node scale + consume-and-reset: out[n,:] = x[n,:] * S[n]; S[n] = 0.
// 8 consecutive threads (same warp) share one S value. __syncwarp() orders
// all 8 loads before the single reset store (independent thread scheduling).
__global__ void scale_kernel(const float4* __restrict__ x4,
                             float4* __restrict__ out4, int n_vec4) {
    int i = blockIdx.x * blockDim.x + threadIdx.x;
    bool ok = i < n_vec4;
    float s = 0.0f;
    float4 v = make_float4(0.f, 0.f, 0.f, 0.f);
    if (ok) {
        s = g_S[i >> 3];
        v = x4[i];
    }
    __syncwarp();
    if (ok) {
        if ((i & 7) == 0) g_S[i >> 3] = 0.0f;  // reset for next invocation
        v.x *= s; v.y *= s; v.z *= s; v.w *= s;
        out4[i] = v;
    }
}

extern "C" void kernel_launch(void* const* d_in, const int* in_sizes, int n_in,
                              void* d_out, int out_size) {
    const int*   edge_index = (const int*)d_in[0];    // [2, E] int32, row-major
    const float* x          = (const float*)d_in[1];  // [N, 32] float32
    const float* W          = (const float*)d_in[2];  // [E] float32

    int E = in_sizes[2];
    int n_nodes = out_size / 32;             // output is [N, 32] float32
    const int* target = edge_index + E;      // row 1 (targets)

    // 1) scatter-add edge weights onto target nodes (g_S arrives zeroed)
    {
        int threads = 256;
        int work = (E + 7) / 8;
        int blocks = (work + threads - 1) / threads;
        edge_kernel<<<blocks, threads>>>(target, W, E);
    }
    // 2) scale node features by accumulated weight, resetting g_S as we go
    {
        int n_vec4 = n_nodes * 8;  // 32 floats / 4
        int threads = 256;
        int blocks = (n_vec4 + threads - 1) / threads;
        scale_kernel<<<blocks, threads>>>((const float4*)x, (float4*)d_out, n_vec4);
    }
}